// round 6
// baseline (speedup 1.0000x reference)
#include <cuda_runtime.h>
#include <math.h>

// ---------------------------------------------------------------------------
// Problem constants
// ---------------------------------------------------------------------------
#define NF 64
#define TT 7
#define H0 192
#define W0 192
#define HW0 (H0 * W0)

// ---------------------------------------------------------------------------
// Scratch layout (single static device buffer; no allocations anywhere)
// ---------------------------------------------------------------------------
#define BIGSZ (7 * 64 * HW0)
#define OFF_FEAT   0
#define OFF_PRED   (OFF_FEAT + BIGSZ)
#define OFF_ALG    (OFF_PRED + BIGSZ)
#define OFF_T0     (OFF_ALG + BIGSZ)
#define OFF_OUT0   (OFF_T0 + 64 * HW0)
#define OFF_OUT1   (OFF_OUT0 + 64 * HW0)
#define OFF_OUT2   (OFF_OUT1 + 64 * 96 * 96)
#define OFF_U24    (OFF_OUT2 + 64 * 48 * 48)
#define OFF_CAT48  (OFF_U24 + 64 * 24 * 24)
#define OFF_C48    (OFF_CAT48 + 128 * 48 * 48)
#define OFF_CAT96  (OFF_C48 + 64 * 48 * 48)
#define OFF_C96    (OFF_CAT96 + 128 * 96 * 96)
#define OFF_FEATF  (OFF_C96 + 64 * 96 * 96)
#define OFF_OFFM   (OFF_FEATF + 64 * HW0)
#define SCRATCH_TOTAL (OFF_OFFM + 189 * HW0)

__device__ float g_scratch[SCRATCH_TOTAL];

enum { EP_NONE = 0, EP_RELU = 1, EP_LEAKY = 2, EP_LEAKY_ADD = 3 };

// ---------------------------------------------------------------------------
// Packed f32x2 helpers (Blackwell FFMA2 path)
// ---------------------------------------------------------------------------
__device__ __forceinline__ unsigned long long pack2s(float v) {
    unsigned long long r;
    asm("mov.b64 %0, {%1, %1};" : "=l"(r) : "f"(v));
    return r;
}
__device__ __forceinline__ unsigned long long pack2(float lo, float hi) {
    unsigned long long r;
    asm("mov.b64 %0, {%1, %2};" : "=l"(r) : "f"(lo), "f"(hi));
    return r;
}
__device__ __forceinline__ void ffma2(unsigned long long& d,
                                      unsigned long long a,
                                      unsigned long long b) {
    asm("fma.rn.f32x2 %0, %1, %2, %0;" : "+l"(d) : "l"(a), "l"(b));
}
__device__ __forceinline__ float2 unpack2(unsigned long long v) {
    float lo, hi;
    asm("mov.b64 {%0, %1}, %2;" : "=f"(lo), "=f"(hi) : "l"(v));
    return make_float2(lo, hi);
}

// ---------------------------------------------------------------------------
// 3x3 stride-1 pad-1 conv, FFMA2 version.
// Tile 32x16 px, 128 threads: thread = 4 x-adjacent px (tx 0..7) x row (ty 0..15),
// 16 couts per block packed as 8 f32x2 co-pairs. CBLK=8 cis per sync round.
// ---------------------------------------------------------------------------
#define CBLK 8
__global__ void __launch_bounds__(128) conv3x3_s1(
    const float* __restrict__ in, const float* __restrict__ wgt,
    const float* __restrict__ bias, float* __restrict__ out,
    int Cin, int Cout, int H, int W, int nChunks,
    int ep, float addScale, const float* __restrict__ addSrc)
{
    __shared__ float s_in[CBLK][18][35];         // padded stride 35: conflict-free
    __shared__ alignas(16) float s_w[CBLK][9][16];

    const int img   = blockIdx.z / nChunks;
    const int chunk = blockIdx.z % nChunks;
    const int ox0 = blockIdx.x * 32, oy0 = blockIdx.y * 16;
    const int tid = threadIdx.x;
    const int tx = tid & 7, ty = tid >> 3;
    const float* inB = in + (size_t)img * Cin * H * W;
    const int coBase = chunk * 16;

    unsigned long long acc[4][8];
#pragma unroll
    for (int p = 0; p < 4; p++)
#pragma unroll
        for (int j = 0; j < 8; j++) acc[p][j] = 0ull;

    for (int c0 = 0; c0 < Cin; c0 += CBLK) {
        const int nc = min(CBLK, Cin - c0);
        // stage inputs (coalesced per-row)
        for (int i = tid; i < nc * 612; i += 128) {
            int cb = i / 612, rem = i - cb * 612;
            int r = rem / 34, c = rem - r * 34;
            int gy = oy0 - 1 + r, gx = ox0 - 1 + c;
            s_in[cb][r][c] = (gy >= 0 && gy < H && gx >= 0 && gx < W)
                ? __ldg(inB + ((size_t)(c0 + cb) * H + gy) * W + gx) : 0.f;
        }
        // stage weights
        for (int i = tid; i < nc * 144; i += 128) {
            int cb = i / 144, rem = i - cb * 144;
            int co = rem / 9, t = rem - co * 9;
            int cog = coBase + co;
            s_w[cb][t][co] = (cog < Cout)
                ? __ldg(wgt + ((size_t)cog * Cin + (c0 + cb)) * 9 + t) : 0.f;
        }
        __syncthreads();

        for (int cb = 0; cb < nc; cb++) {
#pragma unroll
            for (int dy = 0; dy < 3; dy++) {
                unsigned long long xs[6];
#pragma unroll
                for (int j = 0; j < 6; j++)
                    xs[j] = pack2s(s_in[cb][ty + dy][4 * tx + j]);
#pragma unroll
                for (int dx = 0; dx < 3; dx++) {
                    const int t = dy * 3 + dx;
#pragma unroll
                    for (int q2 = 0; q2 < 4; q2++) {
                        ulonglong2 w = *reinterpret_cast<const ulonglong2*>(&s_w[cb][t][4 * q2]);
#pragma unroll
                        for (int p = 0; p < 4; p++) {
                            ffma2(acc[p][2 * q2],     xs[dx + p], w.x);
                            ffma2(acc[p][2 * q2 + 1], xs[dx + p], w.y);
                        }
                    }
                }
            }
        }
        __syncthreads();
    }

    const int oy = oy0 + ty, oxb = ox0 + 4 * tx;
    if (oy >= H || oxb >= W) return;
    const size_t HWs = (size_t)H * W;
    float* ob = out + (size_t)img * Cout * HWs + (size_t)oy * W + oxb;
    const float* as = addSrc ? addSrc + (size_t)oy * W + oxb : nullptr;

#pragma unroll
    for (int j = 0; j < 8; j++) {
        float2 u0 = unpack2(acc[0][j]), u1 = unpack2(acc[1][j]);
        float2 u2 = unpack2(acc[2][j]), u3 = unpack2(acc[3][j]);
#pragma unroll
        for (int s = 0; s < 2; s++) {
            int cog = coBase + 2 * j + s;
            if (cog >= Cout) continue;
            float b = __ldg(bias + cog);
            float4 o;
            o.x = (s ? u0.y : u0.x) + b;
            o.y = (s ? u1.y : u1.x) + b;
            o.z = (s ? u2.y : u2.x) + b;
            o.w = (s ? u3.y : u3.x) + b;
            if (ep == EP_RELU) {
                o.x = fmaxf(o.x, 0.f); o.y = fmaxf(o.y, 0.f);
                o.z = fmaxf(o.z, 0.f); o.w = fmaxf(o.w, 0.f);
            } else if (ep >= EP_LEAKY) {
                o.x = o.x > 0.f ? o.x : 0.1f * o.x;
                o.y = o.y > 0.f ? o.y : 0.1f * o.y;
                o.z = o.z > 0.f ? o.z : 0.1f * o.z;
                o.w = o.w > 0.f ? o.w : 0.1f * o.w;
                if (ep == EP_LEAKY_ADD) {
                    float4 a4 = *reinterpret_cast<const float4*>(as + (size_t)cog * HWs);
                    o.x += addScale * a4.x; o.y += addScale * a4.y;
                    o.z += addScale * a4.z; o.w += addScale * a4.w;
                }
            }
            *reinterpret_cast<float4*>(ob + (size_t)cog * HWs) = o;
        }
    }
}

// ---------------------------------------------------------------------------
// 3x3 stride-2 pad-1 conv. Output tile 16x16, 1 pixel/thread. (unchanged)
// ---------------------------------------------------------------------------
template <int CO>
__global__ void __launch_bounds__(256) conv3x3_s2(
    const float* __restrict__ in, const float* __restrict__ wgt,
    const float* __restrict__ bias, float* __restrict__ out,
    int Cin, int Cout, int Hin, int Win, int Hout, int Wout)
{
    __shared__ float s_in[33][33];
    __shared__ alignas(16) float s_w[9][CO];

    const int chunk = blockIdx.z;
    const int ox0 = blockIdx.x * 16, oy0 = blockIdx.y * 16;
    const int tid = threadIdx.x, tx = tid & 15, ty = tid >> 4;
    const int coBase = chunk * CO;

    float acc[CO];
#pragma unroll
    for (int i = 0; i < CO; i++) acc[i] = 0.f;

    for (int ci = 0; ci < Cin; ci++) {
        const float* ip = in + (size_t)ci * Hin * Win;
        for (int i = tid; i < 33 * 33; i += 256) {
            int r = i / 33, c = i - r * 33;
            int gy = 2 * oy0 - 1 + r, gx = 2 * ox0 - 1 + c;
            s_in[r][c] = (gy >= 0 && gy < Hin && gx >= 0 && gx < Win)
                             ? __ldg(ip + (size_t)gy * Win + gx) : 0.f;
        }
        for (int i = tid; i < 9 * CO; i += 256) {
            int co = i / 9, t = i - co * 9;
            int cog = coBase + co;
            s_w[t][co] = (cog < Cout) ? __ldg(wgt + ((size_t)cog * Cin + ci) * 9 + t) : 0.f;
        }
        __syncthreads();

        float v[9];
#pragma unroll
        for (int t = 0; t < 9; t++) v[t] = s_in[2 * ty + t / 3][2 * tx + t % 3];
#pragma unroll
        for (int t = 0; t < 9; t++) {
#pragma unroll
            for (int q = 0; q < CO / 4; q++) {
                float4 w = *reinterpret_cast<const float4*>(&s_w[t][4 * q]);
                acc[4 * q + 0] += v[t] * w.x; acc[4 * q + 1] += v[t] * w.y;
                acc[4 * q + 2] += v[t] * w.z; acc[4 * q + 3] += v[t] * w.w;
            }
        }
        __syncthreads();
    }

    const int ox = ox0 + tx, oy = oy0 + ty;
    if (ox >= Wout || oy >= Hout) return;
    size_t pbase = (size_t)oy * Wout + ox;
#pragma unroll
    for (int co = 0; co < CO; co++) {
        int cog = coBase + co;
        if (cog >= Cout) break;
        float v = acc[co] + __ldg(bias + cog);
        out[(size_t)cog * Hout * Wout + pbase] = fmaxf(v, 0.f);
    }
}

// ---------------------------------------------------------------------------
// ConvTranspose2d: kernel 4, stride 2, pad 1. (unchanged)
// ---------------------------------------------------------------------------
template <int CO>
__global__ void __launch_bounds__(256) convT4x4_s2(
    const float* __restrict__ in, const float* __restrict__ wgt,
    const float* __restrict__ bias, float* __restrict__ out,
    int Cin, int Cout, int Hin, int Win, int Hout, int Wout)
{
    __shared__ float s_in[10][10];
    __shared__ alignas(16) float s_w[16][CO];

    const int chunk = blockIdx.z;
    const int ox0 = blockIdx.x * 16, oy0 = blockIdx.y * 16;
    const int tid = threadIdx.x, tx = tid & 15, ty = tid >> 4;
    const int coBase = chunk * CO;
    const int iy0 = oy0 / 2 - 1, ix0 = ox0 / 2 - 1;

    const int oy = oy0 + ty, ox = ox0 + tx;
    const int py = (oy + 1) & 1, px = (ox + 1) & 1;
    const int r0 = ((oy + 1 - py) >> 1) - iy0;
    const int r1 = r0 - 1;
    const int c0 = ((ox + 1 - px) >> 1) - ix0;
    const int c1 = c0 - 1;

    float acc[CO];
#pragma unroll
    for (int i = 0; i < CO; i++) acc[i] = 0.f;

    for (int ci = 0; ci < Cin; ci++) {
        const float* ip = in + (size_t)ci * Hin * Win;
        for (int i = tid; i < 100; i += 256) {
            int r = i / 10, c = i - r * 10;
            int gy = iy0 + r, gx = ix0 + c;
            s_in[r][c] = (gy >= 0 && gy < Hin && gx >= 0 && gx < Win)
                             ? __ldg(ip + (size_t)gy * Win + gx) : 0.f;
        }
        for (int i = tid; i < 16 * CO; i += 256) {
            int co = i / 16, t = i - co * 16;
            int cog = coBase + co;
            s_w[t][co] = (cog < Cout) ? __ldg(wgt + ((size_t)ci * Cout + cog) * 16 + t) : 0.f;
        }
        __syncthreads();

        float v00 = s_in[r0][c0], v01 = s_in[r0][c1];
        float v10 = s_in[r1][c0], v11 = s_in[r1][c1];
#pragma unroll
        for (int a = 0; a < 2; a++) {
#pragma unroll
            for (int b = 0; b < 2; b++) {
                float v = a ? (b ? v11 : v10) : (b ? v01 : v00);
                int t = (py + 2 * a) * 4 + (px + 2 * b);
#pragma unroll
                for (int q = 0; q < CO / 4; q++) {
                    float4 w = *reinterpret_cast<const float4*>(&s_w[t][4 * q]);
                    acc[4 * q + 0] += v * w.x; acc[4 * q + 1] += v * w.y;
                    acc[4 * q + 2] += v * w.z; acc[4 * q + 3] += v * w.w;
                }
            }
        }
        __syncthreads();
    }

    if (ox >= Wout || oy >= Hout) return;
    size_t pbase = (size_t)oy * Wout + ox;
#pragma unroll
    for (int co = 0; co < CO; co++) {
        int cog = coBase + co;
        if (cog >= Cout) break;
        float v = acc[co] + __ldg(bias + cog);
        out[(size_t)cog * Hout * Wout + pbase] = fmaxf(v, 0.f);
    }
}

// ---------------------------------------------------------------------------
// Flow warp (unchanged)
// ---------------------------------------------------------------------------
__global__ void flow_warp_kernel(const float* __restrict__ feat,
                                 const float* __restrict__ mv,
                                 float* __restrict__ alg)
{
    const int pix = blockIdx.x * 256 + threadIdx.x;
    if (pix >= HW0) return;
    const int t = blockIdx.y;
    const int y = pix / W0, x = pix - y * W0;

    const float fx = mv[(size_t)t * HW0 * 2 + (size_t)pix * 2 + 0];
    const float fy = mv[(size_t)t * HW0 * 2 + (size_t)pix * 2 + 1];
    const float ys = (float)y + fy;
    const float xs = (float)x + fx;
    const float y0 = floorf(ys), x0 = floorf(xs);
    const float wy = ys - y0, wx = xs - x0;

    float wgt[4]; int off[4]; bool val[4];
#pragma unroll
    for (int i = 0; i < 4; i++) {
        int dy = i >> 1, dx = i & 1;
        float yi = y0 + dy, xi = x0 + dx;
        val[i] = (yi >= 0.f) && (yi <= (float)(H0 - 1)) &&
                 (xi >= 0.f) && (xi <= (float)(W0 - 1));
        wgt[i] = (dy ? wy : 1.f - wy) * (dx ? wx : 1.f - wx);
        off[i] = val[i] ? ((int)yi * W0 + (int)xi) : 0;
    }

    const float* fb = feat + (size_t)t * 64 * HW0;
    float* ob = alg + (size_t)(t + 1) * 64 * HW0 + pix;
    for (int c = 0; c < 64; c++) {
        const float* img = fb + (size_t)c * HW0;
        float acc = 0.f;
#pragma unroll
        for (int i = 0; i < 4; i++)
            if (val[i]) acc += __ldg(img + off[i]) * wgt[i];
        ob[(size_t)c * HW0] = acc;
    }
}

// ---------------------------------------------------------------------------
// Gated fusion (unchanged)
// ---------------------------------------------------------------------------
__global__ void fuse_gate_kernel(const float* __restrict__ feat,
                                 const float* __restrict__ pred,
                                 float* __restrict__ alg)
{
    size_t i = (size_t)blockIdx.x * 256 + threadIdx.x;
    const size_t N = (size_t)7 * 64 * HW0;
    if (i >= N) return;
    size_t rem = i % ((size_t)64 * HW0);
    float ref = feat[(size_t)3 * 64 * HW0 + rem];
    float a = alg[i], p = pred[i];
    float s1 = 1.f / (1.f + expf(-(a * ref)));
    float s2 = 1.f / (1.f + expf(-(p * ref)));
    alg[i] = a * s1 + p * s2;
}

// ---------------------------------------------------------------------------
// Modulated deformable conv, FFMA2 accumulators.
// ---------------------------------------------------------------------------
__global__ void __launch_bounds__(256) deform_kernel(
    const float* __restrict__ lqs, const float* __restrict__ offm,
    const float* __restrict__ dcw, const float* __restrict__ dcb,
    float* __restrict__ out)
{
    __shared__ alignas(16) float s_w[63 * 64];  // [j][o]
    __shared__ float s_b[64];
    const int tid = threadIdx.x;
    for (int i = tid; i < 63 * 64; i += 256) {
        int o = i / 63, j = i - o * 63;
        s_w[j * 64 + o] = dcw[i];
    }
    if (tid < 64) s_b[tid] = dcb[tid];
    __syncthreads();

    const int pix = blockIdx.x * 256 + tid;
    if (pix >= HW0) return;
    const int y = pix / W0, x = pix - y * W0;

    unsigned long long acc[32];
#pragma unroll
    for (int q = 0; q < 32; q++) acc[q] = pack2(s_b[2 * q], s_b[2 * q + 1]);

    for (int g = 0; g < 7; g++) {
        const float* img = lqs + (size_t)g * HW0;
#pragma unroll
        for (int k = 0; k < 9; k++) {
            const int j = g * 9 + k;
            float offy = __ldg(offm + (size_t)(g * 18 + 2 * k + 0) * HW0 + pix);
            float offx = __ldg(offm + (size_t)(g * 18 + 2 * k + 1) * HW0 + pix);
            float mraw = __ldg(offm + (size_t)(126 + j) * HW0 + pix);
            float m = 1.f / (1.f + expf(-mraw));
            float ys = (float)(y + k / 3 - 1) + offy;
            float xs = (float)(x + k % 3 - 1) + offx;
            float y0 = floorf(ys), x0 = floorf(xs);
            float wy = ys - y0, wx = xs - x0;
            float samp = 0.f;
#pragma unroll
            for (int ii = 0; ii < 4; ii++) {
                int dy = ii >> 1, dx = ii & 1;
                float yi = y0 + dy, xi = x0 + dx;
                if (yi >= 0.f && yi <= (float)(H0 - 1) &&
                    xi >= 0.f && xi <= (float)(W0 - 1))
                    samp += __ldg(img + (int)yi * W0 + (int)xi) *
                            ((dy ? wy : 1.f - wy) * (dx ? wx : 1.f - wx));
            }
            unsigned long long mod2 = pack2s(samp * m);
#pragma unroll
            for (int q2 = 0; q2 < 16; q2++) {
                ulonglong2 w = *reinterpret_cast<const ulonglong2*>(&s_w[j * 64 + 4 * q2]);
                ffma2(acc[2 * q2],     mod2, w.x);
                ffma2(acc[2 * q2 + 1], mod2, w.y);
            }
        }
    }
#pragma unroll
    for (int q = 0; q < 32; q++) {
        float2 u = unpack2(acc[q]);
        out[(size_t)(2 * q) * HW0 + pix]     = fmaxf(u.x, 0.f);
        out[(size_t)(2 * q + 1) * HW0 + pix] = fmaxf(u.y, 0.f);
    }
}

// ---------------------------------------------------------------------------
// Host orchestration (graph-capturable)
// ---------------------------------------------------------------------------
extern "C" void kernel_launch(void* const* d_in, const int* in_sizes, int n_in,
                              void* d_out, int out_size)
{
    const float* lqs    = (const float*)d_in[0];
    const float* preds  = (const float*)d_in[1];
    const float* mv     = (const float*)d_in[2];
    const float* bw1    = (const float*)d_in[3];
    const float* bb1    = (const float*)d_in[4];
    const float* bw2    = (const float*)d_in[5];
    const float* bb2    = (const float*)d_in[6];
    const float* dn1_w  = (const float*)d_in[7];
    const float* dn1_b  = (const float*)d_in[8];
    const float* dn2_w  = (const float*)d_in[9];
    const float* dn2_b  = (const float*)d_in[10];
    const float* up1_cw = (const float*)d_in[11];
    const float* up1_cb = (const float*)d_in[12];
    const float* up1_tw = (const float*)d_in[13];
    const float* up1_tb = (const float*)d_in[14];
    const float* up2_cw = (const float*)d_in[15];
    const float* up2_cb = (const float*)d_in[16];
    const float* up2_tw = (const float*)d_in[17];
    const float* up2_tb = (const float*)d_in[18];
    const float* tr_cw  = (const float*)d_in[19];
    const float* tr_cb  = (const float*)d_in[20];
    const float* tr_tw  = (const float*)d_in[21];
    const float* tr_tb  = (const float*)d_in[22];
    const float* ff_w   = (const float*)d_in[23];
    const float* ff_b   = (const float*)d_in[24];
    const float* om_w   = (const float*)d_in[25];
    const float* om_b   = (const float*)d_in[26];
    const float* dc_w   = (const float*)d_in[27];
    const float* dc_b   = (const float*)d_in[28];
    float* outp = (float*)d_out;

    float* S = nullptr;
    cudaGetSymbolAddress((void**)&S, g_scratch);
    float* feat  = S + OFF_FEAT;
    float* pred  = S + OFF_PRED;
    float* alg   = S + OFF_ALG;
    float* t0    = S + OFF_T0;
    float* out0  = S + OFF_OUT0;
    float* out1  = S + OFF_OUT1;
    float* out2  = S + OFF_OUT2;
    float* u24   = S + OFF_U24;
    float* cat48 = S + OFF_CAT48;
    float* c48   = S + OFF_C48;
    float* cat96 = S + OFF_CAT96;
    float* c96   = S + OFF_C96;
    float* featf = S + OFF_FEATF;
    float* offm  = S + OFF_OFFM;

    dim3 blkS1(128), blk(256);

    // Backbone on lqs: 7 images, 1->64 then 64->64 (no activation)
    conv3x3_s1<<<dim3(6, 12, 7 * 4), blkS1>>>(lqs, bw1, bb1, alg, 1, 64, 192, 192, 4,
                                              EP_NONE, 0.f, nullptr);
    conv3x3_s1<<<dim3(6, 12, 7 * 4), blkS1>>>(alg, bw2, bb2, feat, 64, 64, 192, 192, 4,
                                              EP_NONE, 0.f, nullptr);
    // Backbone on preds
    conv3x3_s1<<<dim3(6, 12, 7 * 4), blkS1>>>(preds, bw1, bb1, alg, 1, 64, 192, 192, 4,
                                              EP_NONE, 0.f, nullptr);
    conv3x3_s1<<<dim3(6, 12, 7 * 4), blkS1>>>(alg, bw2, bb2, pred, 64, 64, 192, 192, 4,
                                              EP_NONE, 0.f, nullptr);

    // aligned[0] = feat[0]; aligned[1..6] = warp(feat[0..5], mv)
    cudaMemcpyAsync(alg, feat, (size_t)64 * HW0 * sizeof(float),
                    cudaMemcpyDeviceToDevice, 0);
    flow_warp_kernel<<<dim3(HW0 / 256, 6), blk>>>(feat, mv, alg);

    // alg := a1 + a2 (gated), in place
    fuse_gate_kernel<<<(unsigned)(((size_t)7 * 64 * HW0 + 255) / 256), blk>>>(feat, pred, alg);

    // out0 = 0.1*leaky(conv448(alg)) + leaky(conv448(feat))
    conv3x3_s1<<<dim3(6, 12, 4), blkS1>>>(alg, ff_w, ff_b, t0, 448, 64, 192, 192, 4,
                                          EP_LEAKY, 0.f, nullptr);
    conv3x3_s1<<<dim3(6, 12, 4), blkS1>>>(feat, ff_w, ff_b, out0, 448, 64, 192, 192, 4,
                                          EP_LEAKY_ADD, 0.1f, t0);

    // Down path
    conv3x3_s2<16><<<dim3(6, 6, 4), blk>>>(out0, dn1_w, dn1_b, out1, 64, 64, 192, 192, 96, 96);
    conv3x3_s2<16><<<dim3(3, 3, 4), blk>>>(out1, dn2_w, dn2_b, out2, 64, 64, 96, 96, 48, 48);
    conv3x3_s2<16><<<dim3(2, 2, 4), blk>>>(out2, tr_cw, tr_cb, u24, 64, 64, 48, 48, 24, 24);

    // Up path with skip concats
    convT4x4_s2<32><<<dim3(3, 3, 2), blk>>>(u24, tr_tw, tr_tb, cat48, 64, 64, 24, 24, 48, 48);
    cudaMemcpyAsync(cat48 + (size_t)64 * 48 * 48, out2,
                    (size_t)64 * 48 * 48 * sizeof(float), cudaMemcpyDeviceToDevice, 0);
    conv3x3_s1<<<dim3(2, 3, 4), blkS1>>>(cat48, up2_cw, up2_cb, c48, 128, 64, 48, 48, 4,
                                         EP_RELU, 0.f, nullptr);
    convT4x4_s2<32><<<dim3(6, 6, 2), blk>>>(c48, up2_tw, up2_tb, cat96, 64, 64, 48, 48, 96, 96);
    cudaMemcpyAsync(cat96 + (size_t)64 * 96 * 96, out1,
                    (size_t)64 * 96 * 96 * sizeof(float), cudaMemcpyDeviceToDevice, 0);
    conv3x3_s1<<<dim3(3, 6, 4), blkS1>>>(cat96, up1_cw, up1_cb, c96, 128, 64, 96, 96, 4,
                                         EP_RELU, 0.f, nullptr);
    convT4x4_s2<32><<<dim3(12, 12, 2), blk>>>(c96, up1_tw, up1_tb, featf, 64, 64, 96, 96, 192, 192);

    // Offsets + masks (Cout=189 -> 12 chunks of 16)
    conv3x3_s1<<<dim3(6, 12, 12), blkS1>>>(featf, om_w, om_b, offm, 64, 189, 192, 192, 12,
                                           EP_NONE, 0.f, nullptr);

    // Modulated deformable conv + ReLU -> output
    deform_kernel<<<HW0 / 256, blk>>>(lqs, offm, dc_w, dc_b, outp);
}

// round 7
// speedup vs baseline: 1.4900x; 1.4900x over previous
#include <cuda_runtime.h>
#include <math.h>

// ---------------------------------------------------------------------------
// Problem constants
// ---------------------------------------------------------------------------
#define NF 64
#define TT 7
#define H0 192
#define W0 192
#define HW0 (H0 * W0)

// ---------------------------------------------------------------------------
// Scratch layout (single static device buffer; no allocations anywhere)
// ---------------------------------------------------------------------------
#define BIGSZ (7 * 64 * HW0)
#define OFF_FEAT   0
#define OFF_PRED   (OFF_FEAT + BIGSZ)
#define OFF_ALG    (OFF_PRED + BIGSZ)           // conv1 scratch (lqs) / aligned
#define OFF_ALG2   (OFF_ALG + BIGSZ)            // conv1 scratch (preds)
#define OFF_OUT0   (OFF_ALG2 + BIGSZ)
#define OFF_OUT1   (OFF_OUT0 + 64 * HW0)
#define OFF_OUT2   (OFF_OUT1 + 64 * 96 * 96)
#define OFF_U24    (OFF_OUT2 + 64 * 48 * 48)
#define OFF_CAT48  (OFF_U24 + 64 * 24 * 24)
#define OFF_C48    (OFF_CAT48 + 128 * 48 * 48)
#define OFF_CAT96  (OFF_C48 + 64 * 48 * 48)
#define OFF_C96    (OFF_CAT96 + 128 * 96 * 96)
#define OFF_FEATF  (OFF_C96 + 64 * 96 * 96)
#define OFF_OFFM   (OFF_FEATF + 64 * HW0)
#define SCRATCH_TOTAL (OFF_OFFM + 189 * HW0)

__device__ float g_scratch[SCRATCH_TOTAL];

enum { EP_NONE = 0, EP_RELU = 1 };

// ---------------------------------------------------------------------------
// Packed f32x2 helpers (Blackwell FFMA2 path)
// ---------------------------------------------------------------------------
typedef unsigned long long ull_t;
__device__ __forceinline__ ull_t pack2s(float v) {
    ull_t r;
    asm("mov.b64 %0, {%1, %1};" : "=l"(r) : "f"(v));
    return r;
}
__device__ __forceinline__ ull_t pack2(float lo, float hi) {
    ull_t r;
    asm("mov.b64 %0, {%1, %2};" : "=l"(r) : "f"(lo), "f"(hi));
    return r;
}
__device__ __forceinline__ void ffma2(ull_t& d, ull_t a, ull_t b) {
    asm("fma.rn.f32x2 %0, %1, %2, %0;" : "+l"(d) : "l"(a), "l"(b));
}
__device__ __forceinline__ float2 unpack2(ull_t v) {
    float lo, hi;
    asm("mov.b64 {%0, %1}, %2;" : "=f"(lo), "=f"(hi) : "l"(v));
    return make_float2(lo, hi);
}
__device__ __forceinline__ float fsigmoid(float x) {
    return 1.f / (1.f + __expf(-x));
}

// ---------------------------------------------------------------------------
// 3x3 stride-1 pad-1 conv, FFMA2, 256 threads.
// Output tile 32x16: thread = 2 x-adjacent px (tx 0..15) x row (ty 0..15).
// 16 couts per chunk (8 f32x2 pairs). CBLK=8 cis per sync round.
// ---------------------------------------------------------------------------
#define CBLK 8
__global__ void __launch_bounds__(256) conv3x3_s1(
    const float* __restrict__ in, const float* __restrict__ wgt,
    const float* __restrict__ bias, float* __restrict__ out,
    int Cin, int Cout, int H, int W, int nChunks, int ep)
{
    __shared__ float s_in[CBLK][18][35];
    __shared__ alignas(16) float s_w[CBLK][9][16];

    const int img   = blockIdx.z / nChunks;
    const int chunk = blockIdx.z % nChunks;
    const int ox0 = blockIdx.x * 32, oy0 = blockIdx.y * 16;
    const int tid = threadIdx.x;
    const int tx = tid & 15, ty = tid >> 4;
    const float* inB = in + (size_t)img * Cin * H * W;
    const int coBase = chunk * 16;

    ull_t acc0[8], acc1[8];
#pragma unroll
    for (int j = 0; j < 8; j++) { acc0[j] = 0ull; acc1[j] = 0ull; }

    for (int c0 = 0; c0 < Cin; c0 += CBLK) {
        const int nc = min(CBLK, Cin - c0);
        for (int i = tid; i < nc * 612; i += 256) {
            int cb = i / 612, rem = i - cb * 612;
            int r = rem / 34, c = rem - r * 34;
            int gy = oy0 - 1 + r, gx = ox0 - 1 + c;
            s_in[cb][r][c] = (gy >= 0 && gy < H && gx >= 0 && gx < W)
                ? __ldg(inB + ((size_t)(c0 + cb) * H + gy) * W + gx) : 0.f;
        }
        for (int i = tid; i < nc * 144; i += 256) {
            int cb = i / 144, rem = i - cb * 144;
            int co = rem / 9, t = rem - co * 9;
            int cog = coBase + co;
            s_w[cb][t][co] = (cog < Cout)
                ? __ldg(wgt + ((size_t)cog * Cin + (c0 + cb)) * 9 + t) : 0.f;
        }
        __syncthreads();

        for (int cb = 0; cb < nc; cb++) {
#pragma unroll
            for (int dy = 0; dy < 3; dy++) {
                ull_t ps[4];
#pragma unroll
                for (int j = 0; j < 4; j++)
                    ps[j] = pack2s(s_in[cb][ty + dy][2 * tx + j]);
#pragma unroll
                for (int dx = 0; dx < 3; dx++) {
                    const int t = dy * 3 + dx;
#pragma unroll
                    for (int q2 = 0; q2 < 4; q2++) {
                        ulonglong2 w = *reinterpret_cast<const ulonglong2*>(&s_w[cb][t][4 * q2]);
                        ffma2(acc0[2 * q2],     ps[dx],     w.x);
                        ffma2(acc0[2 * q2 + 1], ps[dx],     w.y);
                        ffma2(acc1[2 * q2],     ps[dx + 1], w.x);
                        ffma2(acc1[2 * q2 + 1], ps[dx + 1], w.y);
                    }
                }
            }
        }
        __syncthreads();
    }

    const int oy = oy0 + ty, oxb = ox0 + 2 * tx;
    if (oy >= H || oxb >= W) return;
    const size_t HWs = (size_t)H * W;
    float* ob = out + (size_t)img * Cout * HWs + (size_t)oy * W + oxb;

#pragma unroll
    for (int j = 0; j < 8; j++) {
        float2 u0 = unpack2(acc0[j]), u1 = unpack2(acc1[j]);
#pragma unroll
        for (int s = 0; s < 2; s++) {
            int cog = coBase + 2 * j + s;
            if (cog >= Cout) continue;
            float b = __ldg(bias + cog);
            float2 o;
            o.x = (s ? u0.y : u0.x) + b;
            o.y = (s ? u1.y : u1.x) + b;
            if (ep == EP_RELU) { o.x = fmaxf(o.x, 0.f); o.y = fmaxf(o.y, 0.f); }
            *reinterpret_cast<float2*>(ob + (size_t)cog * HWs) = o;
        }
    }
}

// ---------------------------------------------------------------------------
// Dual-input shared-weight 3x3 conv for the fusion pair:
// out = 0.1*leaky(conv(inA)+b) + leaky(conv(inF)+b)
// ---------------------------------------------------------------------------
__global__ void __launch_bounds__(256) conv3x3_s1_dual(
    const float* __restrict__ inA, const float* __restrict__ inF,
    const float* __restrict__ wgt, const float* __restrict__ bias,
    float* __restrict__ out, int Cin, int Cout)
{
    __shared__ float s_a[CBLK][18][35];
    __shared__ float s_f[CBLK][18][35];
    __shared__ alignas(16) float s_w[CBLK][9][16];

    const int chunk = blockIdx.z;
    const int ox0 = blockIdx.x * 32, oy0 = blockIdx.y * 16;
    const int tid = threadIdx.x;
    const int tx = tid & 15, ty = tid >> 4;
    const int coBase = chunk * 16;
    const int H = H0, W = W0;

    ull_t aA0[8], aA1[8], aF0[8], aF1[8];
#pragma unroll
    for (int j = 0; j < 8; j++) { aA0[j] = aA1[j] = aF0[j] = aF1[j] = 0ull; }

    for (int c0 = 0; c0 < Cin; c0 += CBLK) {
        const int nc = min(CBLK, Cin - c0);
        for (int i = tid; i < nc * 612; i += 256) {
            int cb = i / 612, rem = i - cb * 612;
            int r = rem / 34, c = rem - r * 34;
            int gy = oy0 - 1 + r, gx = ox0 - 1 + c;
            bool ok = (gy >= 0 && gy < H && gx >= 0 && gx < W);
            size_t gidx = ((size_t)(c0 + cb) * H + gy) * W + gx;
            s_a[cb][r][c] = ok ? __ldg(inA + gidx) : 0.f;
            s_f[cb][r][c] = ok ? __ldg(inF + gidx) : 0.f;
        }
        for (int i = tid; i < nc * 144; i += 256) {
            int cb = i / 144, rem = i - cb * 144;
            int co = rem / 9, t = rem - co * 9;
            s_w[cb][t][co] = __ldg(wgt + ((size_t)(coBase + co) * Cin + (c0 + cb)) * 9 + t);
        }
        __syncthreads();

        for (int cb = 0; cb < nc; cb++) {
#pragma unroll
            for (int dy = 0; dy < 3; dy++) {
                ull_t pa[4], pf[4];
#pragma unroll
                for (int j = 0; j < 4; j++) {
                    pa[j] = pack2s(s_a[cb][ty + dy][2 * tx + j]);
                    pf[j] = pack2s(s_f[cb][ty + dy][2 * tx + j]);
                }
#pragma unroll
                for (int dx = 0; dx < 3; dx++) {
                    const int t = dy * 3 + dx;
#pragma unroll
                    for (int q2 = 0; q2 < 4; q2++) {
                        ulonglong2 w = *reinterpret_cast<const ulonglong2*>(&s_w[cb][t][4 * q2]);
                        ffma2(aA0[2 * q2],     pa[dx],     w.x);
                        ffma2(aA0[2 * q2 + 1], pa[dx],     w.y);
                        ffma2(aA1[2 * q2],     pa[dx + 1], w.x);
                        ffma2(aA1[2 * q2 + 1], pa[dx + 1], w.y);
                        ffma2(aF0[2 * q2],     pf[dx],     w.x);
                        ffma2(aF0[2 * q2 + 1], pf[dx],     w.y);
                        ffma2(aF1[2 * q2],     pf[dx + 1], w.x);
                        ffma2(aF1[2 * q2 + 1], pf[dx + 1], w.y);
                    }
                }
            }
        }
        __syncthreads();
    }

    const int oy = oy0 + ty, oxb = ox0 + 2 * tx;
    const size_t HWs = (size_t)H * W;
    float* ob = out + (size_t)oy * W + oxb;

#pragma unroll
    for (int j = 0; j < 8; j++) {
        float2 A0 = unpack2(aA0[j]), A1 = unpack2(aA1[j]);
        float2 F0 = unpack2(aF0[j]), F1 = unpack2(aF1[j]);
#pragma unroll
        for (int s = 0; s < 2; s++) {
            int cog = coBase + 2 * j + s;
            float b = __ldg(bias + cog);
            float va0 = (s ? A0.y : A0.x) + b;
            float va1 = (s ? A1.y : A1.x) + b;
            float vf0 = (s ? F0.y : F0.x) + b;
            float vf1 = (s ? F1.y : F1.x) + b;
            va0 = va0 > 0.f ? va0 : 0.1f * va0;
            va1 = va1 > 0.f ? va1 : 0.1f * va1;
            vf0 = vf0 > 0.f ? vf0 : 0.1f * vf0;
            vf1 = vf1 > 0.f ? vf1 : 0.1f * vf1;
            float2 o = make_float2(0.1f * va0 + vf0, 0.1f * va1 + vf1);
            *reinterpret_cast<float2*>(ob + (size_t)cog * HWs) = o;
        }
    }
}

// ---------------------------------------------------------------------------
// 3x3 stride-2 pad-1 conv. Output tile 16x16, 1 pixel/thread.
// ---------------------------------------------------------------------------
template <int CO>
__global__ void __launch_bounds__(256) conv3x3_s2(
    const float* __restrict__ in, const float* __restrict__ wgt,
    const float* __restrict__ bias, float* __restrict__ out,
    int Cin, int Cout, int Hin, int Win, int Hout, int Wout)
{
    __shared__ float s_in[33][33];
    __shared__ alignas(16) float s_w[9][CO];

    const int chunk = blockIdx.z;
    const int ox0 = blockIdx.x * 16, oy0 = blockIdx.y * 16;
    const int tid = threadIdx.x, tx = tid & 15, ty = tid >> 4;
    const int coBase = chunk * CO;

    float acc[CO];
#pragma unroll
    for (int i = 0; i < CO; i++) acc[i] = 0.f;

    for (int ci = 0; ci < Cin; ci++) {
        const float* ip = in + (size_t)ci * Hin * Win;
        for (int i = tid; i < 33 * 33; i += 256) {
            int r = i / 33, c = i - r * 33;
            int gy = 2 * oy0 - 1 + r, gx = 2 * ox0 - 1 + c;
            s_in[r][c] = (gy >= 0 && gy < Hin && gx >= 0 && gx < Win)
                             ? __ldg(ip + (size_t)gy * Win + gx) : 0.f;
        }
        for (int i = tid; i < 9 * CO; i += 256) {
            int co = i / 9, t = i - co * 9;
            int cog = coBase + co;
            s_w[t][co] = (cog < Cout) ? __ldg(wgt + ((size_t)cog * Cin + ci) * 9 + t) : 0.f;
        }
        __syncthreads();

        float v[9];
#pragma unroll
        for (int t = 0; t < 9; t++) v[t] = s_in[2 * ty + t / 3][2 * tx + t % 3];
#pragma unroll
        for (int t = 0; t < 9; t++) {
#pragma unroll
            for (int q = 0; q < CO / 4; q++) {
                float4 w = *reinterpret_cast<const float4*>(&s_w[t][4 * q]);
                acc[4 * q + 0] += v[t] * w.x; acc[4 * q + 1] += v[t] * w.y;
                acc[4 * q + 2] += v[t] * w.z; acc[4 * q + 3] += v[t] * w.w;
            }
        }
        __syncthreads();
    }

    const int ox = ox0 + tx, oy = oy0 + ty;
    if (ox >= Wout || oy >= Hout) return;
    size_t pbase = (size_t)oy * Wout + ox;
#pragma unroll
    for (int co = 0; co < CO; co++) {
        int cog = coBase + co;
        if (cog >= Cout) break;
        float v = acc[co] + __ldg(bias + cog);
        out[(size_t)cog * Hout * Wout + pbase] = fmaxf(v, 0.f);
    }
}

// ---------------------------------------------------------------------------
// ConvTranspose2d: kernel 4, stride 2, pad 1. Always ReLU.
// ---------------------------------------------------------------------------
template <int CO>
__global__ void __launch_bounds__(256) convT4x4_s2(
    const float* __restrict__ in, const float* __restrict__ wgt,
    const float* __restrict__ bias, float* __restrict__ out,
    int Cin, int Cout, int Hin, int Win, int Hout, int Wout)
{
    __shared__ float s_in[10][10];
    __shared__ alignas(16) float s_w[16][CO];

    const int chunk = blockIdx.z;
    const int ox0 = blockIdx.x * 16, oy0 = blockIdx.y * 16;
    const int tid = threadIdx.x, tx = tid & 15, ty = tid >> 4;
    const int coBase = chunk * CO;
    const int iy0 = oy0 / 2 - 1, ix0 = ox0 / 2 - 1;

    const int oy = oy0 + ty, ox = ox0 + tx;
    const int py = (oy + 1) & 1, px = (ox + 1) & 1;
    const int r0 = ((oy + 1 - py) >> 1) - iy0;
    const int r1 = r0 - 1;
    const int c0 = ((ox + 1 - px) >> 1) - ix0;
    const int c1 = c0 - 1;

    float acc[CO];
#pragma unroll
    for (int i = 0; i < CO; i++) acc[i] = 0.f;

    for (int ci = 0; ci < Cin; ci++) {
        const float* ip = in + (size_t)ci * Hin * Win;
        for (int i = tid; i < 100; i += 256) {
            int r = i / 10, c = i - r * 10;
            int gy = iy0 + r, gx = ix0 + c;
            s_in[r][c] = (gy >= 0 && gy < Hin && gx >= 0 && gx < Win)
                             ? __ldg(ip + (size_t)gy * Win + gx) : 0.f;
        }
        for (int i = tid; i < 16 * CO; i += 256) {
            int co = i / 16, t = i - co * 16;
            int cog = coBase + co;
            s_w[t][co] = (cog < Cout) ? __ldg(wgt + ((size_t)ci * Cout + cog) * 16 + t) : 0.f;
        }
        __syncthreads();

        float v00 = s_in[r0][c0], v01 = s_in[r0][c1];
        float v10 = s_in[r1][c0], v11 = s_in[r1][c1];
#pragma unroll
        for (int a = 0; a < 2; a++) {
#pragma unroll
            for (int b = 0; b < 2; b++) {
                float v = a ? (b ? v11 : v10) : (b ? v01 : v00);
                int t = (py + 2 * a) * 4 + (px + 2 * b);
#pragma unroll
                for (int q = 0; q < CO / 4; q++) {
                    float4 w = *reinterpret_cast<const float4*>(&s_w[t][4 * q]);
                    acc[4 * q + 0] += v * w.x; acc[4 * q + 1] += v * w.y;
                    acc[4 * q + 2] += v * w.z; acc[4 * q + 3] += v * w.w;
                }
            }
        }
        __syncthreads();
    }

    if (ox >= Wout || oy >= Hout) return;
    size_t pbase = (size_t)oy * Wout + ox;
#pragma unroll
    for (int co = 0; co < CO; co++) {
        int cog = coBase + co;
        if (cog >= Cout) break;
        float v = acc[co] + __ldg(bias + cog);
        out[(size_t)cog * Hout * Wout + pbase] = fmaxf(v, 0.f);
    }
}

// ---------------------------------------------------------------------------
// Flow warp
// ---------------------------------------------------------------------------
__global__ void flow_warp_kernel(const float* __restrict__ feat,
                                 const float* __restrict__ mv,
                                 float* __restrict__ alg)
{
    const int pix = blockIdx.x * 256 + threadIdx.x;
    if (pix >= HW0) return;
    const int t = blockIdx.y;
    const int y = pix / W0, x = pix - y * W0;

    const float fx = mv[(size_t)t * HW0 * 2 + (size_t)pix * 2 + 0];
    const float fy = mv[(size_t)t * HW0 * 2 + (size_t)pix * 2 + 1];
    const float ys = (float)y + fy;
    const float xs = (float)x + fx;
    const float y0 = floorf(ys), x0 = floorf(xs);
    const float wy = ys - y0, wx = xs - x0;

    float wgt[4]; int off[4]; bool val[4];
#pragma unroll
    for (int i = 0; i < 4; i++) {
        int dy = i >> 1, dx = i & 1;
        float yi = y0 + dy, xi = x0 + dx;
        val[i] = (yi >= 0.f) && (yi <= (float)(H0 - 1)) &&
                 (xi >= 0.f) && (xi <= (float)(W0 - 1));
        wgt[i] = (dy ? wy : 1.f - wy) * (dx ? wx : 1.f - wx);
        off[i] = val[i] ? ((int)yi * W0 + (int)xi) : 0;
    }

    const float* fb = feat + (size_t)t * 64 * HW0;
    float* ob = alg + (size_t)(t + 1) * 64 * HW0 + pix;
    for (int c = 0; c < 64; c++) {
        const float* img = fb + (size_t)c * HW0;
        float acc = 0.f;
#pragma unroll
        for (int i = 0; i < 4; i++)
            if (val[i]) acc += __ldg(img + off[i]) * wgt[i];
        ob[(size_t)c * HW0] = acc;
    }
}

// ---------------------------------------------------------------------------
// Gated fusion, float4 + __expf: alg := alg*sig(alg*ref) + pred*sig(pred*ref)
// ---------------------------------------------------------------------------
__global__ void fuse_gate_kernel(const float* __restrict__ feat,
                                 const float* __restrict__ pred,
                                 float* __restrict__ alg)
{
    const size_t N4 = (size_t)7 * 64 * HW0 / 4;
    size_t i = (size_t)blockIdx.x * 256 + threadIdx.x;
    if (i >= N4) return;
    size_t rem = i % ((size_t)64 * HW0 / 4);
    float4 ref = reinterpret_cast<const float4*>(feat + (size_t)3 * 64 * HW0)[rem];
    float4 a = reinterpret_cast<float4*>(alg)[i];
    float4 p = reinterpret_cast<const float4*>(pred)[i];
    float4 o;
    o.x = a.x * fsigmoid(a.x * ref.x) + p.x * fsigmoid(p.x * ref.x);
    o.y = a.y * fsigmoid(a.y * ref.y) + p.y * fsigmoid(p.y * ref.y);
    o.z = a.z * fsigmoid(a.z * ref.z) + p.z * fsigmoid(p.z * ref.z);
    o.w = a.w * fsigmoid(a.w * ref.w) + p.w * fsigmoid(p.w * ref.w);
    reinterpret_cast<float4*>(alg)[i] = o;
}

// ---------------------------------------------------------------------------
// Modulated deformable conv, FFMA2 accumulators + __expf sigmoid.
// ---------------------------------------------------------------------------
__global__ void __launch_bounds__(256) deform_kernel(
    const float* __restrict__ lqs, const float* __restrict__ offm,
    const float* __restrict__ dcw, const float* __restrict__ dcb,
    float* __restrict__ out)
{
    __shared__ alignas(16) float s_w[63 * 64];  // [j][o]
    __shared__ float s_b[64];
    const int tid = threadIdx.x;
    for (int i = tid; i < 63 * 64; i += 256) {
        int o = i / 63, j = i - o * 63;
        s_w[j * 64 + o] = dcw[i];
    }
    if (tid < 64) s_b[tid] = dcb[tid];
    __syncthreads();

    const int pix = blockIdx.x * 256 + tid;
    if (pix >= HW0) return;
    const int y = pix / W0, x = pix - y * W0;

    ull_t acc[32];
#pragma unroll
    for (int q = 0; q < 32; q++) acc[q] = pack2(s_b[2 * q], s_b[2 * q + 1]);

    for (int g = 0; g < 7; g++) {
        const float* img = lqs + (size_t)g * HW0;
#pragma unroll
        for (int k = 0; k < 9; k++) {
            const int j = g * 9 + k;
            float offy = __ldg(offm + (size_t)(g * 18 + 2 * k + 0) * HW0 + pix);
            float offx = __ldg(offm + (size_t)(g * 18 + 2 * k + 1) * HW0 + pix);
            float mraw = __ldg(offm + (size_t)(126 + j) * HW0 + pix);
            float m = fsigmoid(mraw);
            float ys = (float)(y + k / 3 - 1) + offy;
            float xs = (float)(x + k % 3 - 1) + offx;
            float y0 = floorf(ys), x0 = floorf(xs);
            float wy = ys - y0, wx = xs - x0;
            float samp = 0.f;
#pragma unroll
            for (int ii = 0; ii < 4; ii++) {
                int dy = ii >> 1, dx = ii & 1;
                float yi = y0 + dy, xi = x0 + dx;
                if (yi >= 0.f && yi <= (float)(H0 - 1) &&
                    xi >= 0.f && xi <= (float)(W0 - 1))
                    samp += __ldg(img + (int)yi * W0 + (int)xi) *
                            ((dy ? wy : 1.f - wy) * (dx ? wx : 1.f - wx));
            }
            ull_t mod2 = pack2s(samp * m);
#pragma unroll
            for (int q2 = 0; q2 < 16; q2++) {
                ulonglong2 w = *reinterpret_cast<const ulonglong2*>(&s_w[j * 64 + 4 * q2]);
                ffma2(acc[2 * q2],     mod2, w.x);
                ffma2(acc[2 * q2 + 1], mod2, w.y);
            }
        }
    }
#pragma unroll
    for (int q = 0; q < 32; q++) {
        float2 u = unpack2(acc[q]);
        out[(size_t)(2 * q) * HW0 + pix]     = fmaxf(u.x, 0.f);
        out[(size_t)(2 * q + 1) * HW0 + pix] = fmaxf(u.y, 0.f);
    }
}

// ---------------------------------------------------------------------------
// Host orchestration (graph-capturable)
// ---------------------------------------------------------------------------
extern "C" void kernel_launch(void* const* d_in, const int* in_sizes, int n_in,
                              void* d_out, int out_size)
{
    const float* lqs    = (const float*)d_in[0];
    const float* preds  = (const float*)d_in[1];
    const float* mv     = (const float*)d_in[2];
    const float* bw1    = (const float*)d_in[3];
    const float* bb1    = (const float*)d_in[4];
    const float* bw2    = (const float*)d_in[5];
    const float* bb2    = (const float*)d_in[6];
    const float* dn1_w  = (const float*)d_in[7];
    const float* dn1_b  = (const float*)d_in[8];
    const float* dn2_w  = (const float*)d_in[9];
    const float* dn2_b  = (const float*)d_in[10];
    const float* up1_cw = (const float*)d_in[11];
    const float* up1_cb = (const float*)d_in[12];
    const float* up1_tw = (const float*)d_in[13];
    const float* up1_tb = (const float*)d_in[14];
    const float* up2_cw = (const float*)d_in[15];
    const float* up2_cb = (const float*)d_in[16];
    const float* up2_tw = (const float*)d_in[17];
    const float* up2_tb = (const float*)d_in[18];
    const float* tr_cw  = (const float*)d_in[19];
    const float* tr_cb  = (const float*)d_in[20];
    const float* tr_tw  = (const float*)d_in[21];
    const float* tr_tb  = (const float*)d_in[22];
    const float* ff_w   = (const float*)d_in[23];
    const float* ff_b   = (const float*)d_in[24];
    const float* om_w   = (const float*)d_in[25];
    const float* om_b   = (const float*)d_in[26];
    const float* dc_w   = (const float*)d_in[27];
    const float* dc_b   = (const float*)d_in[28];
    float* outp = (float*)d_out;

    float* S = nullptr;
    cudaGetSymbolAddress((void**)&S, g_scratch);
    float* feat  = S + OFF_FEAT;   // conv2 out: imgs 0..6 (lqs)
    float* pred  = S + OFF_PRED;   // conv2 out: imgs 7..13 (preds) — contiguous after feat
    float* alg   = S + OFF_ALG;    // conv1 scratch (lqs), later aligned buffer
    float* alg2  = S + OFF_ALG2;   // conv1 scratch (preds)
    float* out0  = S + OFF_OUT0;
    float* out1  = S + OFF_OUT1;
    float* out2  = S + OFF_OUT2;
    float* u24   = S + OFF_U24;
    float* cat48 = S + OFF_CAT48;
    float* c48   = S + OFF_C48;
    float* cat96 = S + OFF_CAT96;
    float* c96   = S + OFF_C96;
    float* featf = S + OFF_FEATF;
    float* offm  = S + OFF_OFFM;

    dim3 blk(256);

    // Backbone conv1 (1->64) on lqs and preds -> contiguous scratch [alg|alg2]
    conv3x3_s1<<<dim3(6, 12, 7 * 4), blk>>>(lqs,   bw1, bb1, alg,  1, 64, 192, 192, 4, EP_NONE);
    conv3x3_s1<<<dim3(6, 12, 7 * 4), blk>>>(preds, bw1, bb1, alg2, 1, 64, 192, 192, 4, EP_NONE);
    // Backbone conv2 (64->64), 14 images in ONE launch -> [feat|pred]
    conv3x3_s1<<<dim3(6, 12, 14 * 4), blk>>>(alg, bw2, bb2, feat, 64, 64, 192, 192, 4, EP_NONE);

    // aligned[0] = feat[0]; aligned[1..6] = warp(feat[0..5], mv)  (reuses alg)
    cudaMemcpyAsync(alg, feat, (size_t)64 * HW0 * sizeof(float),
                    cudaMemcpyDeviceToDevice, 0);
    flow_warp_kernel<<<dim3(HW0 / 256, 6), blk>>>(feat, mv, alg);

    // alg := a1 + a2 (gated), in place
    fuse_gate_kernel<<<(unsigned)(((size_t)7 * 64 * HW0 / 4 + 255) / 256), blk>>>(feat, pred, alg);

    // out0 = 0.1*leaky(conv448(alg)) + leaky(conv448(feat)) — one dual kernel
    conv3x3_s1_dual<<<dim3(6, 12, 4), blk>>>(alg, feat, ff_w, ff_b, out0, 448, 64);

    // Down path
    conv3x3_s2<16><<<dim3(6, 6, 4), blk>>>(out0, dn1_w, dn1_b, out1, 64, 64, 192, 192, 96, 96);
    conv3x3_s2<16><<<dim3(3, 3, 4), blk>>>(out1, dn2_w, dn2_b, out2, 64, 64, 96, 96, 48, 48);
    conv3x3_s2<16><<<dim3(2, 2, 4), blk>>>(out2, tr_cw, tr_cb, u24, 64, 64, 48, 48, 24, 24);

    // Up path with skip concats
    convT4x4_s2<32><<<dim3(3, 3, 2), blk>>>(u24, tr_tw, tr_tb, cat48, 64, 64, 24, 24, 48, 48);
    cudaMemcpyAsync(cat48 + (size_t)64 * 48 * 48, out2,
                    (size_t)64 * 48 * 48 * sizeof(float), cudaMemcpyDeviceToDevice, 0);
    conv3x3_s1<<<dim3(2, 3, 4), blk>>>(cat48, up2_cw, up2_cb, c48, 128, 64, 48, 48, 4, EP_RELU);
    convT4x4_s2<32><<<dim3(6, 6, 2), blk>>>(c48, up2_tw, up2_tb, cat96, 64, 64, 48, 48, 96, 96);
    cudaMemcpyAsync(cat96 + (size_t)64 * 96 * 96, out1,
                    (size_t)64 * 96 * 96 * sizeof(float), cudaMemcpyDeviceToDevice, 0);
    conv3x3_s1<<<dim3(3, 6, 4), blk>>>(cat96, up1_cw, up1_cb, c96, 128, 64, 96, 96, 4, EP_RELU);
    convT4x4_s2<32><<<dim3(12, 12, 2), blk>>>(c96, up1_tw, up1_tb, featf, 64, 64, 96, 96, 192, 192);

    // Offsets + masks (Cout=189 -> 12 chunks of 16)
    conv3x3_s1<<<dim3(6, 12, 12), blk>>>(featf, om_w, om_b, offm, 64, 189, 192, 192, 12, EP_NONE);

    // Modulated deformable conv + ReLU -> output
    deform_kernel<<<HW0 / 256, blk>>>(lqs, offm, dc_w, dc_b, outp);
}